// round 4
// baseline (speedup 1.0000x reference)
#include <cuda_runtime.h>

// ---------------------------------------------------------------------------
// DecoderBlock: x:(8,2048,32), H=4, hd=8. fp32, f32x2 packed FMA.
// Attention: uniform 256q x 256k work units, split-K via global fp32 red.add.
// ---------------------------------------------------------------------------

constexpr int B_  = 8;
constexpr int T_  = 2048;
constexpr int D_  = 32;
constexpr int BT_ = B_ * T_;

__device__ float g_h[BT_ * D_];   // LN1 output
__device__ float g_q[BT_ * D_];   // (B,H,T,8), pre-scaled by log2e/sqrt(8)
__device__ float g_k[BT_ * D_];
__device__ float g_v[BT_ * D_];
__device__ float g_o[BT_ * D_];   // UNNORMALIZED attention out (B*T,32), atomically accumulated
__device__ float g_l[BT_];        // softmax denominators, (B,H,T) = bh*2048+t

typedef unsigned long long u64;

static __device__ __forceinline__ u64 ffma2(u64 a, u64 b, u64 c) {
    u64 d; asm("fma.rn.f32x2 %0, %1, %2, %3;" : "=l"(d) : "l"(a), "l"(b), "l"(c));
    return d;
}
static __device__ __forceinline__ u64 fmul2(u64 a, u64 b) {
    u64 d; asm("mul.rn.f32x2 %0, %1, %2;" : "=l"(d) : "l"(a), "l"(b));
    return d;
}
static __device__ __forceinline__ u64 fadd2(u64 a, u64 b) {
    u64 d; asm("add.rn.f32x2 %0, %1, %2;" : "=l"(d) : "l"(a), "l"(b));
    return d;
}
static __device__ __forceinline__ u64 pack2(float x, float y) {
    u64 d; asm("mov.b64 %0, {%1, %2};" : "=l"(d) : "f"(x), "f"(y));
    return d;
}
static __device__ __forceinline__ float2 unpack2(u64 d) {
    float2 r; asm("mov.b64 {%0, %1}, %2;" : "=f"(r.x), "=f"(r.y) : "l"(d));
    return r;
}
static __device__ __forceinline__ float ex2f(float x) {
    float r; asm("ex2.approx.ftz.f32 %0, %1;" : "=f"(r) : "f"(x));
    return r;
}
static __device__ __forceinline__ void red4(float* p, float a, float b, float c, float d) {
    asm volatile("red.global.add.v4.f32 [%0], {%1, %2, %3, %4};"
                 :: "l"(p), "f"(a), "f"(b), "f"(c), "f"(d) : "memory");
}
static __device__ __forceinline__ void red1(float* p, float a) {
    asm volatile("red.global.add.f32 [%0], %1;" :: "l"(p), "f"(a) : "memory");
}

// ---------------------------------------------------------------------------
// Kernel 1: LN1 + QKV. 64 tokens/block, 256 threads, grid 256.
// Also zeroes g_o / g_l for the attention accumulators.
// ---------------------------------------------------------------------------
__global__ __launch_bounds__(256) void k_ln_qkv(
    const float* __restrict__ x,
    const float* __restrict__ Wq, const float* __restrict__ Wk,
    const float* __restrict__ Wv,
    const float* __restrict__ g1, const float* __restrict__ b1)
{
    __shared__ __align__(16) float sh_h[64][33];
    __shared__ __align__(16) float sh_w[32][96];   // [d][qkv*32 + head*8 + kk]

    const int tid = threadIdx.x;
    const int t0  = blockIdx.x * 64;
    const int gid = blockIdx.x * 256 + tid;        // 0..65535

    // zero accumulators (written by k_attn atomics later)
    {
        float4 z = make_float4(0.f, 0.f, 0.f, 0.f);
        float4* o4 = (float4*)g_o;
        o4[gid * 2]     = z;
        o4[gid * 2 + 1] = z;
        g_l[gid] = 0.f;
    }

    for (int i = tid; i < 3072; i += 256) {
        int type = i >> 10, rem = i & 1023;
        int head = rem >> 8, d = (rem >> 3) & 31, kk = rem & 7;
        const float* W = (type == 0) ? Wq : (type == 1) ? Wk : Wv;
        sh_w[d][type * 32 + head * 8 + kk] = W[(head * 32 + d) * 8 + kk];
    }

    // LN: 4 lanes per token, 8 values each
    const int tk = tid >> 2, part = tid & 3;
    const int t  = t0 + tk;
    const int c0 = part * 8;
    const float4* xr = (const float4*)(x + t * 32 + c0);
    float4 v0 = xr[0], v1 = xr[1];
    float s  = v0.x + v0.y + v0.z + v0.w + v1.x + v1.y + v1.z + v1.w;
    float ss = v0.x*v0.x + v0.y*v0.y + v0.z*v0.z + v0.w*v0.w
             + v1.x*v1.x + v1.y*v1.y + v1.z*v1.z + v1.w*v1.w;
    s  += __shfl_xor_sync(0xffffffffu, s, 1);
    ss += __shfl_xor_sync(0xffffffffu, ss, 1);
    s  += __shfl_xor_sync(0xffffffffu, s, 2);
    ss += __shfl_xor_sync(0xffffffffu, ss, 2);
    const float mu = s * 0.03125f;
    const float rs = rsqrtf(ss * 0.03125f - mu * mu + 1e-5f);
    float hv[8];
    {
        const float* vv = (const float*)&v0;
        #pragma unroll
        for (int i = 0; i < 4; i++)
            hv[i] = (vv[i] - mu) * rs * __ldg(g1 + c0 + i) + __ldg(b1 + c0 + i);
        const float* vw = (const float*)&v1;
        #pragma unroll
        for (int i = 0; i < 4; i++)
            hv[4+i] = (vw[i] - mu) * rs * __ldg(g1 + c0 + 4 + i) + __ldg(b1 + c0 + 4 + i);
    }
    #pragma unroll
    for (int i = 0; i < 8; i++) sh_h[tk][c0 + i] = hv[i];
    float4* hg = (float4*)(g_h + t * 32 + c0);
    hg[0] = make_float4(hv[0], hv[1], hv[2], hv[3]);
    hg[1] = make_float4(hv[4], hv[5], hv[6], hv[7]);
    __syncthreads();

    // GEMM: thread = 2 tokens x 12 outs (weights amortized over 2 tokens)
    const int to = tid >> 3;   // 0..31 -> tokens 2to, 2to+1
    const int oo = tid & 7;    // 0..7  -> 12 outs
    u64 acc0[6] = {0,0,0,0,0,0}, acc1[6] = {0,0,0,0,0,0};

    #pragma unroll 4
    for (int kd = 0; kd < 32; kd++) {
        float a0 = sh_h[2 * to][kd];
        float a1 = sh_h[2 * to + 1][kd];
        u64 ap0 = pack2(a0, a0), ap1 = pack2(a1, a1);
        const ulonglong2* wr = (const ulonglong2*)&sh_w[kd][oo * 12];
        ulonglong2 w0 = wr[0], w1 = wr[1], w2 = wr[2];
        u64 wv[6] = {w0.x, w0.y, w1.x, w1.y, w2.x, w2.y};
        #pragma unroll
        for (int i = 0; i < 6; i++) {
            acc0[i] = ffma2(ap0, wv[i], acc0[i]);
            acc1[i] = ffma2(ap1, wv[i], acc1[i]);
        }
    }

    const float QS = 0.51006973f;            // log2(e)/sqrt(8)
    const int b  = t0 >> 11;
    const int tt = (t0 & 2047) + 2 * to;
    #pragma unroll
    for (int i2 = 0; i2 < 6; i2++) {
        int o    = oo * 12 + 2 * i2;
        int type = o >> 5;
        int head = (o >> 3) & 3;
        int kk   = o & 7;
        float* base = (type == 0) ? g_q : (type == 1) ? g_k : g_v;
        float sc = (type == 0) ? QS : 1.f;
        float2 u0 = unpack2(acc0[i2]);
        float2 u1 = unpack2(acc1[i2]);
        float* p = base + ((b * 4 + head) * 2048 + tt) * 8 + kk;
        *(float2*)(p)     = make_float2(u0.x * sc, u0.y * sc);
        *(float2*)(p + 8) = make_float2(u1.x * sc, u1.y * sc);
    }
}

// ---------------------------------------------------------------------------
// Kernel 2: causal attention, uniform split-K work units.
// Block = one (bh, qt2, ku) unit: 256 queries x 256 keys. 128 threads,
// 2 queries each. Partial (o, l) accumulated into g_o/g_l via red.add.
// Units per bh = sum_{qt2=0..7}(qt2+1) = 36. Grid = 32*36 = 1152.
// ---------------------------------------------------------------------------
static __device__ __forceinline__ void attn_pair(
    const u64* __restrict__ q, const ulonglong2& kA, const ulonglong2& kB,
    const ulonglong2& kC, const ulonglong2& kD,
    const ulonglong2& va0, const ulonglong2& va1,
    const ulonglong2& vb0, const ulonglong2& vb1,
    u64* __restrict__ o, float& l, bool m0, bool m1)
{
    u64 e = fmul2(q[0], kA.x); e = ffma2(q[2], kB.x, e);
    e = ffma2(q[4], kC.x, e);  e = ffma2(q[6], kD.x, e);
    u64 od = fmul2(q[1], kA.y); od = ffma2(q[3], kB.y, od);
    od = ffma2(q[5], kC.y, od); od = ffma2(q[7], kD.y, od);
    float2 d = unpack2(fadd2(e, od));
    float p0 = m0 ? ex2f(d.x) : 0.f;
    float p1 = m1 ? ex2f(d.y) : 0.f;
    l += p0 + p1;
    u64 pp0 = pack2(p0, p0), pp1 = pack2(p1, p1);
    o[0] = ffma2(pp0, va0.x, o[0]); o[1] = ffma2(pp0, va0.y, o[1]);
    o[2] = ffma2(pp0, va1.x, o[2]); o[3] = ffma2(pp0, va1.y, o[3]);
    o[0] = ffma2(pp1, vb0.x, o[0]); o[1] = ffma2(pp1, vb0.y, o[1]);
    o[2] = ffma2(pp1, vb1.x, o[2]); o[3] = ffma2(pp1, vb1.y, o[3]);
}

__global__ __launch_bounds__(128) void k_attn()
{
    __shared__ __align__(16) u64    sKp[128 * 8];   // [keypair][dim] packed (key even, key odd)
    __shared__ __align__(16) float4 sV [256 * 2];   // [key][2 halves of 8 dims]

    const int ht  = threadIdx.x;
    const int bid = blockIdx.x;
    const int bh  = bid / 36;
    int r = bid - bh * 36;
    // qt2 = largest q with q(q+1)/2 <= r
    int qt2 = (int)((sqrtf(8.f * (float)r + 1.f) - 1.f) * 0.5f);
    while ((qt2 + 1) * (qt2 + 2) / 2 <= r) qt2++;
    while (qt2 * (qt2 + 1) / 2 > r) qt2--;
    const int ku  = r - qt2 * (qt2 + 1) / 2;
    const int t0q = qt2 * 256;
    const int k0  = ku * 256;

    // stage K (transposed, key-paired) and V
    {
        const float4* kg = (const float4*)(g_k + (bh * T_ + k0 + 2 * ht) * 8);
        float4 ka0 = kg[0], ka1 = kg[1];   // key 2*ht
        float4 kb0 = kg[2], kb1 = kg[3];   // key 2*ht+1
        u64* row = &sKp[ht * 8];
        row[0] = pack2(ka0.x, kb0.x); row[1] = pack2(ka0.y, kb0.y);
        row[2] = pack2(ka0.z, kb0.z); row[3] = pack2(ka0.w, kb0.w);
        row[4] = pack2(ka1.x, kb1.x); row[5] = pack2(ka1.y, kb1.y);
        row[6] = pack2(ka1.z, kb1.z); row[7] = pack2(ka1.w, kb1.w);
        const float4* vg = (const float4*)(g_v + bh * T_ * 8);
        sV[ht]       = vg[k0 * 2 + ht];
        sV[ht + 128] = vg[k0 * 2 + 128 + ht];
        sV[ht + 256] = vg[k0 * 2 + 256 + ht];
        sV[ht + 384] = vg[k0 * 2 + 384 + ht];
    }

    const int tqa = t0q + ht;          // query a
    const int tqb = t0q + 128 + ht;    // query b
    u64 qa[8], qq[8];
    {
        const float4* pa = (const float4*)(g_q + (bh * T_ + tqa) * 8);
        float4 a0 = pa[0], a1 = pa[1];
        qa[0]=pack2(a0.x,a0.x); qa[1]=pack2(a0.y,a0.y); qa[2]=pack2(a0.z,a0.z); qa[3]=pack2(a0.w,a0.w);
        qa[4]=pack2(a1.x,a1.x); qa[5]=pack2(a1.y,a1.y); qa[6]=pack2(a1.z,a1.z); qa[7]=pack2(a1.w,a1.w);
        const float4* pb = (const float4*)(g_q + (bh * T_ + tqb) * 8);
        float4 b0 = pb[0], b1 = pb[1];
        qq[0]=pack2(b0.x,b0.x); qq[1]=pack2(b0.y,b0.y); qq[2]=pack2(b0.z,b0.z); qq[3]=pack2(b0.w,b0.w);
        qq[4]=pack2(b1.x,b1.x); qq[5]=pack2(b1.y,b1.y); qq[6]=pack2(b1.z,b1.z); qq[7]=pack2(b1.w,b1.w);
    }

    u64 oa[4] = {0,0,0,0}, ob[4] = {0,0,0,0};
    float la = 0.f, lb = 0.f;

    __syncthreads();

    if (ku < qt2) {
        // full unit
        #pragma unroll 2
        for (int sp = 0; sp < 128; sp++) {
            const ulonglong2* kr = (const ulonglong2*)&sKp[sp * 8];
            ulonglong2 kA = kr[0], kB = kr[1], kC = kr[2], kD = kr[3];
            const ulonglong2* vr = (const ulonglong2*)&sV[4 * sp];
            ulonglong2 va0 = vr[0], va1 = vr[1], vb0 = vr[2], vb1 = vr[3];
            attn_pair(qa, kA, kB, kC, kD, va0, va1, vb0, vb1, oa, la, true, true);
            attn_pair(qq, kA, kB, kC, kD, va0, va1, vb0, vb1, ob, lb, true, true);
        }
    } else {
        // diagonal unit: keys rel [0,128) -> a masked, b full; [128,256) -> a none, b masked
        for (int sp = 0; sp < 64; sp++) {
            const int rel = 2 * sp;
            const ulonglong2* kr = (const ulonglong2*)&sKp[sp * 8];
            ulonglong2 kA = kr[0], kB = kr[1], kC = kr[2], kD = kr[3];
            const ulonglong2* vr = (const ulonglong2*)&sV[4 * sp];
            ulonglong2 va0 = vr[0], va1 = vr[1], vb0 = vr[2], vb1 = vr[3];
            attn_pair(qa, kA, kB, kC, kD, va0, va1, vb0, vb1, oa, la,
                      rel <= ht, rel + 1 <= ht);
            attn_pair(qq, kA, kB, kC, kD, va0, va1, vb0, vb1, ob, lb, true, true);
        }
        for (int sp = 64; sp < 128; sp++) {
            const int rel = 2 * sp;
            const ulonglong2* kr = (const ulonglong2*)&sKp[sp * 8];
            ulonglong2 kA = kr[0], kB = kr[1], kC = kr[2], kD = kr[3];
            const ulonglong2* vr = (const ulonglong2*)&sV[4 * sp];
            ulonglong2 va0 = vr[0], va1 = vr[1], vb0 = vr[2], vb1 = vr[3];
            attn_pair(qq, kA, kB, kC, kD, va0, va1, vb0, vb1, ob, lb,
                      rel <= 128 + ht, rel + 1 <= 128 + ht);
        }
    }

    // merge partials into global accumulators
    const int b = bh >> 2, h = bh & 3;
    {
        float2 u0 = unpack2(oa[0]), u1 = unpack2(oa[1]);
        float2 u2 = unpack2(oa[2]), u3 = unpack2(oa[3]);
        float* p = g_o + ((b * T_ + tqa) * 32 + h * 8);
        red4(p,     u0.x, u0.y, u1.x, u1.y);
        red4(p + 4, u2.x, u2.y, u3.x, u3.y);
        red1(g_l + bh * T_ + tqa, la);
    }
    {
        float2 u0 = unpack2(ob[0]), u1 = unpack2(ob[1]);
        float2 u2 = unpack2(ob[2]), u3 = unpack2(ob[3]);
        float* p = g_o + ((b * T_ + tqb) * 32 + h * 8);
        red4(p,     u0.x, u0.y, u1.x, u1.y);
        red4(p + 4, u2.x, u2.y, u3.x, u3.y);
        red1(g_l + bh * T_ + tqb, lb);
    }
}

// ---------------------------------------------------------------------------
// Kernel 3: proj + residual + LN2 + FFN + residual. 64 tokens, 256 threads.
// Normalizes the attention accumulator by g_l on load.
// ---------------------------------------------------------------------------
constexpr int SM3_FLOATS = 1024 + 4096 + 4096 + 128 + 128 + 64 * 33 + 64 * 129;
constexpr int SM3_BYTES  = SM3_FLOATS * 4;

__global__ __launch_bounds__(256) void k_post(
    float* __restrict__ out,
    const float* __restrict__ Wp, const float* __restrict__ bp,
    const float* __restrict__ W1, const float* __restrict__ b1v,
    const float* __restrict__ W2, const float* __restrict__ b2v,
    const float* __restrict__ g2, const float* __restrict__ bt2)
{
    extern __shared__ float sm[];
    float* sWp  = sm;                 // [kd][32]
    float* sW1  = sWp + 1024;         // [k][128]
    float* sW2  = sW1 + 4096;         // [k][32]
    float* sB   = sW2 + 4096;         // 0:bproj 32:b2 64:ln2_g 96:ln2_b
    float* sb1  = sB + 128;
    float* sX   = sb1 + 128;          // 64 x 33
    float* sHid = sX + 64 * 33;       // 64 x 129

    const int tid = threadIdx.x;
    const int t0  = blockIdx.x * 64;

    for (int i = tid; i < 1024; i += 256) sWp[i] = Wp[i];
    for (int i = tid; i < 4096; i += 256) sW1[i] = W1[i];
    for (int i = tid; i < 4096; i += 256) sW2[i] = W2[i];
    if (tid < 32) { sB[tid] = bp[tid]; sB[32 + tid] = b2v[tid];
                    sB[64 + tid] = g2[tid]; sB[96 + tid] = bt2[tid]; }
    if (tid >= 128 && tid < 256) sb1[tid - 128] = b1v[tid - 128];

    for (int i = tid; i < 512; i += 256) {
        int row = i >> 3, c4 = i & 7;
        int t = t0 + row;
        int head = c4 >> 1;
        int bb = t >> 11, tl = t & 2047;
        float inv = __fdividef(1.f, g_l[(bb * 4 + head) * 2048 + tl]);
        float4 v = ((const float4*)(g_o + t * 32))[c4];
        float* d = &sX[row * 33 + c4 * 4];
        d[0] = v.x * inv; d[1] = v.y * inv; d[2] = v.z * inv; d[3] = v.w * inv;
    }
    __syncthreads();

    // ---- stage A: x1 = h + o@Wproj + bproj ; h2 = LN2(x1) ----
    const int tr = tid >> 2, q4 = tid & 3;   // token, col-quarter (8 cols)
    const int gt = t0 + tr;
    u64 accp[4] = {0,0,0,0};

    #pragma unroll 4
    for (int kd = 0; kd < 32; kd++) {
        float a = sX[tr * 33 + kd];
        u64 ap = pack2(a, a);
        const ulonglong2* wr = (const ulonglong2*)&sWp[kd * 32 + q4 * 8];
        ulonglong2 w0 = wr[0], w1 = wr[1];
        accp[0] = ffma2(ap, w0.x, accp[0]); accp[1] = ffma2(ap, w0.y, accp[1]);
        accp[2] = ffma2(ap, w1.x, accp[2]); accp[3] = ffma2(ap, w1.y, accp[3]);
    }
    float xv[8];
    {
        const float4* hp = (const float4*)(g_h + gt * 32 + q4 * 8);
        float4 h0 = hp[0], h1 = hp[1];
        float hh[8] = {h0.x, h0.y, h0.z, h0.w, h1.x, h1.y, h1.z, h1.w};
        #pragma unroll
        for (int i = 0; i < 4; i++) {
            float2 u = unpack2(accp[i]);
            xv[2*i]   = hh[2*i]   + u.x + sB[q4 * 8 + 2*i];
            xv[2*i+1] = hh[2*i+1] + u.y + sB[q4 * 8 + 2*i + 1];
        }
    }
    float s = 0.f, ss = 0.f;
    #pragma unroll
    for (int i = 0; i < 8; i++) { s += xv[i]; ss += xv[i] * xv[i]; }
    s  += __shfl_xor_sync(0xffffffffu, s, 1);
    ss += __shfl_xor_sync(0xffffffffu, ss, 1);
    s  += __shfl_xor_sync(0xffffffffu, s, 2);
    ss += __shfl_xor_sync(0xffffffffu, ss, 2);
    const float mu = s * 0.03125f;
    const float rs = rsqrtf(ss * 0.03125f - mu * mu + 1e-5f);
    float h2r[8];
    #pragma unroll
    for (int i = 0; i < 8; i++)
        h2r[i] = (xv[i] - mu) * rs * sB[64 + q4 * 8 + i] + sB[96 + q4 * 8 + i];

    __syncthreads();
    #pragma unroll
    for (int i = 0; i < 8; i++) sX[tr * 33 + q4 * 8 + i] = h2r[i];
    __syncthreads();

    // ---- stage B: hid = relu(h2 @ W1 + b1) ----
    const int ttb = tid >> 4;   // 0..15 -> 4 tokens each
    const int oo  = tid & 15;   // 8 outs each
    u64 accB[4][4];
    #pragma unroll
    for (int j = 0; j < 4; j++)
        #pragma unroll
        for (int i = 0; i < 4; i++) accB[j][i] = 0;

    #pragma unroll 4
    for (int k = 0; k < 32; k++) {
        u64 ap[4];
        #pragma unroll
        for (int j = 0; j < 4; j++) {
            float a = sX[(ttb * 4 + j) * 33 + k];
            ap[j] = pack2(a, a);
        }
        const ulonglong2* wr = (const ulonglong2*)&sW1[k * 128 + oo * 8];
        ulonglong2 ww0 = wr[0], ww1 = wr[1];
        u64 wv[4] = {ww0.x, ww0.y, ww1.x, ww1.y};
        #pragma unroll
        for (int j = 0; j < 4; j++)
            #pragma unroll
            for (int i = 0; i < 4; i++)
                accB[j][i] = ffma2(ap[j], wv[i], accB[j][i]);
    }
    #pragma unroll
    for (int j = 0; j < 4; j++)
        #pragma unroll
        for (int i = 0; i < 4; i++) {
            float2 u = unpack2(accB[j][i]);
            float* d = &sHid[(ttb * 4 + j) * 129 + oo * 8 + 2 * i];
            d[0] = fmaxf(u.x + sb1[oo * 8 + 2 * i], 0.f);
            d[1] = fmaxf(u.y + sb1[oo * 8 + 2 * i + 1], 0.f);
        }
    __syncthreads();

    // ---- stage C: out = h2 + hid @ W2 + b2 ----
    u64 accC[4] = {0,0,0,0};
    #pragma unroll 4
    for (int k = 0; k < 128; k++) {
        float a = sHid[tr * 129 + k];
        u64 ap = pack2(a, a);
        const ulonglong2* wr = (const ulonglong2*)&sW2[k * 32 + q4 * 8];
        ulonglong2 w0 = wr[0], w1 = wr[1];
        accC[0] = ffma2(ap, w0.x, accC[0]); accC[1] = ffma2(ap, w0.y, accC[1]);
        accC[2] = ffma2(ap, w1.x, accC[2]); accC[3] = ffma2(ap, w1.y, accC[3]);
    }
    float cc[8];
    #pragma unroll
    for (int i = 0; i < 4; i++) {
        float2 u = unpack2(accC[i]);
        cc[2*i] = u.x; cc[2*i+1] = u.y;
    }
    float4* op = (float4*)(out + gt * 32 + q4 * 8);
    const float* b2p = &sB[32 + q4 * 8];
    op[0] = make_float4(h2r[0] + cc[0] + b2p[0], h2r[1] + cc[1] + b2p[1],
                        h2r[2] + cc[2] + b2p[2], h2r[3] + cc[3] + b2p[3]);
    op[1] = make_float4(h2r[4] + cc[4] + b2p[4], h2r[5] + cc[5] + b2p[5],
                        h2r[6] + cc[6] + b2p[6], h2r[7] + cc[7] + b2p[7]);
}

// ---------------------------------------------------------------------------
extern "C" void kernel_launch(void* const* d_in, const int* in_sizes, int n_in,
                              void* d_out, int out_size)
{
    const float* x   = (const float*)d_in[0];
    const float* Wq  = (const float*)d_in[1];
    const float* Wk  = (const float*)d_in[2];
    const float* Wv  = (const float*)d_in[3];
    const float* Wp  = (const float*)d_in[4];
    const float* bp  = (const float*)d_in[5];
    const float* g1  = (const float*)d_in[6];
    const float* b1  = (const float*)d_in[7];
    const float* W1  = (const float*)d_in[8];
    const float* b1f = (const float*)d_in[9];
    const float* W2  = (const float*)d_in[10];
    const float* b2f = (const float*)d_in[11];
    const float* g2  = (const float*)d_in[12];
    const float* bt2 = (const float*)d_in[13];
    float* out = (float*)d_out;

    cudaFuncSetAttribute((const void*)k_post,
                         cudaFuncAttributeMaxDynamicSharedMemorySize, SM3_BYTES);

    k_ln_qkv<<<BT_ / 64, 256>>>(x, Wq, Wk, Wv, g1, b1);

    k_attn<<<32 * 36, 128>>>();

    k_post<<<BT_ / 64, 256, SM3_BYTES>>>(out, Wp, bp, W1, b1f, W2, b2f, g2, bt2);
}

// round 5
// speedup vs baseline: 1.3971x; 1.3971x over previous
#include <cuda_runtime.h>

// ---------------------------------------------------------------------------
// DecoderBlock: x:(8,2048,32), H=4, hd=8. fp32, f32x2 packed FMA.
// Attention: causal-balanced pairing — block (bh, j) handles query tiles
// j and 15-j (uniform 17 key-tile visits per block), key-parity split halves.
// ---------------------------------------------------------------------------

constexpr int B_  = 8;
constexpr int T_  = 2048;
constexpr int D_  = 32;
constexpr int BT_ = B_ * T_;

__device__ float g_h[BT_ * D_];   // LN1 output
__device__ float g_q[BT_ * D_];   // (B,H,T,8), pre-scaled by log2e/sqrt(8)
__device__ float g_k[BT_ * D_];
__device__ float g_v[BT_ * D_];
__device__ float g_o[BT_ * D_];   // attention out (B*T,32), normalized

typedef unsigned long long u64;

static __device__ __forceinline__ u64 ffma2(u64 a, u64 b, u64 c) {
    u64 d; asm("fma.rn.f32x2 %0, %1, %2, %3;" : "=l"(d) : "l"(a), "l"(b), "l"(c));
    return d;
}
static __device__ __forceinline__ u64 fmul2(u64 a, u64 b) {
    u64 d; asm("mul.rn.f32x2 %0, %1, %2;" : "=l"(d) : "l"(a), "l"(b));
    return d;
}
static __device__ __forceinline__ u64 fadd2(u64 a, u64 b) {
    u64 d; asm("add.rn.f32x2 %0, %1, %2;" : "=l"(d) : "l"(a), "l"(b));
    return d;
}
static __device__ __forceinline__ u64 pack2(float x, float y) {
    u64 d; asm("mov.b64 %0, {%1, %2};" : "=l"(d) : "f"(x), "f"(y));
    return d;
}
static __device__ __forceinline__ float2 unpack2(u64 d) {
    float2 r; asm("mov.b64 {%0, %1}, %2;" : "=f"(r.x), "=f"(r.y) : "l"(d));
    return r;
}
static __device__ __forceinline__ float ex2f(float x) {
    float r; asm("ex2.approx.ftz.f32 %0, %1;" : "=f"(r) : "f"(x));
    return r;
}

// ---------------------------------------------------------------------------
// Kernel 1: LN1 + QKV. 32 tokens/block, 128 threads, grid 512.  (round-2 best)
// ---------------------------------------------------------------------------
__global__ __launch_bounds__(128) void k_ln_qkv(
    const float* __restrict__ x,
    const float* __restrict__ Wq, const float* __restrict__ Wk,
    const float* __restrict__ Wv,
    const float* __restrict__ g1, const float* __restrict__ b1)
{
    __shared__ __align__(16) float sh_h[32][33];
    __shared__ __align__(16) float sh_w[32][96];   // [d][qkv*32 + head*8 + kk]

    const int tid = threadIdx.x;
    const int t0  = blockIdx.x * 32;

    for (int i = tid; i < 3072; i += 128) {
        int type = i >> 10, rem = i & 1023;
        int head = rem >> 8, d = (rem >> 3) & 31, kk = rem & 7;
        const float* W = (type == 0) ? Wq : (type == 1) ? Wk : Wv;
        sh_w[d][type * 32 + head * 8 + kk] = W[(head * 32 + d) * 8 + kk];
    }

    // LN: 4 lanes per token
    const int tk = tid >> 2, part = tid & 3;
    const int t  = t0 + tk;
    const int c0 = part * 8;
    const float4* xr = (const float4*)(x + t * 32 + c0);
    float4 v0 = xr[0], v1 = xr[1];
    float s  = v0.x + v0.y + v0.z + v0.w + v1.x + v1.y + v1.z + v1.w;
    float ss = v0.x*v0.x + v0.y*v0.y + v0.z*v0.z + v0.w*v0.w
             + v1.x*v1.x + v1.y*v1.y + v1.z*v1.z + v1.w*v1.w;
    s  += __shfl_xor_sync(0xffffffffu, s, 1);
    ss += __shfl_xor_sync(0xffffffffu, ss, 1);
    s  += __shfl_xor_sync(0xffffffffu, s, 2);
    ss += __shfl_xor_sync(0xffffffffu, ss, 2);
    const float mu = s * 0.03125f;
    const float rs = rsqrtf(ss * 0.03125f - mu * mu + 1e-5f);
    float hv[8];
    {
        const float* vv = (const float*)&v0;
        #pragma unroll
        for (int i = 0; i < 4; i++)
            hv[i] = (vv[i] - mu) * rs * __ldg(g1 + c0 + i) + __ldg(b1 + c0 + i);
        const float* vw = (const float*)&v1;
        #pragma unroll
        for (int i = 0; i < 4; i++)
            hv[4 + i] = (vw[i] - mu) * rs * __ldg(g1 + c0 + 4 + i) + __ldg(b1 + c0 + 4 + i);
    }
    #pragma unroll
    for (int i = 0; i < 8; i++) sh_h[tk][c0 + i] = hv[i];
    float4* hr = (float4*)(g_h + t * 32 + c0);
    hr[0] = make_float4(hv[0], hv[1], hv[2], hv[3]);
    hr[1] = make_float4(hv[4], hv[5], hv[6], hv[7]);
    __syncthreads();

    // GEMM: thread = 2 tokens x 12 outs (packed pairs)
    const int to = tid >> 3;   // 0..15
    const int oo = tid & 7;    // 0..7
    u64 acc0[6] = {0,0,0,0,0,0}, acc1[6] = {0,0,0,0,0,0};

    #pragma unroll 4
    for (int kd = 0; kd < 32; kd++) {
        float a0 = sh_h[2 * to][kd];
        float a1 = sh_h[2 * to + 1][kd];
        u64 ap0 = pack2(a0, a0), ap1 = pack2(a1, a1);
        const ulonglong2* wr = (const ulonglong2*)&sh_w[kd][oo * 12];
        ulonglong2 w0 = wr[0], w1 = wr[1], w2 = wr[2];
        u64 wv[6] = {w0.x, w0.y, w1.x, w1.y, w2.x, w2.y};
        #pragma unroll
        for (int i = 0; i < 6; i++) {
            acc0[i] = ffma2(ap0, wv[i], acc0[i]);
            acc1[i] = ffma2(ap1, wv[i], acc1[i]);
        }
    }

    const float QS = 0.51006973f;            // log2(e)/sqrt(8)
    const int b   = t0 >> 11;
    const int ttl = (t0 & 2047) + 2 * to;
    #pragma unroll
    for (int i2 = 0; i2 < 6; i2++) {
        int o    = oo * 12 + 2 * i2;
        int type = o >> 5;
        int head = (o >> 3) & 3;
        int kk   = o & 7;
        float* base = (type == 0) ? g_q : (type == 1) ? g_k : g_v;
        float sc = (type == 0) ? QS : 1.f;
        float2 u0 = unpack2(acc0[i2]);
        float2 u1 = unpack2(acc1[i2]);
        float* p = base + ((b * 4 + head) * 2048 + ttl) * 8 + kk;
        *(float2*)(p)     = make_float2(u0.x * sc, u0.y * sc);
        *(float2*)(p + 8) = make_float2(u1.x * sc, u1.y * sc);
    }
}

// ---------------------------------------------------------------------------
// Kernel 2: causal attention, balanced pairing.
// grid (32, 8), 256 threads. Block (bh, j): query tiles j and 15-j.
// half = key-tile parity; per-half partials merged via smem at end.
// ---------------------------------------------------------------------------
static __device__ __forceinline__ void attn_pair(
    const u64* __restrict__ q, const ulonglong2& kA, const ulonglong2& kB,
    const ulonglong2& kC, const ulonglong2& kD,
    const ulonglong2& va0, const ulonglong2& va1,
    const ulonglong2& vb0, const ulonglong2& vb1,
    u64* __restrict__ o, float& l, bool m0, bool m1)
{
    u64 e = fmul2(q[0], kA.x); e = ffma2(q[2], kB.x, e);
    e = ffma2(q[4], kC.x, e);  e = ffma2(q[6], kD.x, e);
    u64 od = fmul2(q[1], kA.y); od = ffma2(q[3], kB.y, od);
    od = ffma2(q[5], kC.y, od); od = ffma2(q[7], kD.y, od);
    float2 d = unpack2(fadd2(e, od));
    float p0 = m0 ? ex2f(d.x) : 0.f;
    float p1 = m1 ? ex2f(d.y) : 0.f;
    l += p0 + p1;
    u64 pp0 = pack2(p0, p0), pp1 = pack2(p1, p1);
    o[0] = ffma2(pp0, va0.x, o[0]); o[1] = ffma2(pp0, va0.y, o[1]);
    o[2] = ffma2(pp0, va1.x, o[2]); o[3] = ffma2(pp0, va1.y, o[3]);
    o[0] = ffma2(pp1, vb0.x, o[0]); o[1] = ffma2(pp1, vb0.y, o[1]);
    o[2] = ffma2(pp1, vb1.x, o[2]); o[3] = ffma2(pp1, vb1.y, o[3]);
}

__global__ __launch_bounds__(256) void k_attn()
{
    __shared__ __align__(16) float  sKp[2][64 * 20];  // [half][keypair][8 u64 + pad]
    __shared__ __align__(16) float4 sV [2][256];
    __shared__ float sPart[128 * 20];

    const int tid  = threadIdx.x;
    const int half = tid >> 7;
    const int ht   = tid & 127;
    const int bh   = blockIdx.x;
    const int j    = blockIdx.y;       // 0..7 -> tiles j and 15-j
    const int jhi  = 15 - j;
    const int tqa  = j * 128 + ht;
    const int tqb  = jhi * 128 + ht;

    u64 qa[8], qq[8];
    {
        const float4* pa = (const float4*)(g_q + (bh * T_ + tqa) * 8);
        float4 a0 = pa[0], a1 = pa[1];
        qa[0]=pack2(a0.x,a0.x); qa[1]=pack2(a0.y,a0.y); qa[2]=pack2(a0.z,a0.z); qa[3]=pack2(a0.w,a0.w);
        qa[4]=pack2(a1.x,a1.x); qa[5]=pack2(a1.y,a1.y); qa[6]=pack2(a1.z,a1.z); qa[7]=pack2(a1.w,a1.w);
        const float4* pb = (const float4*)(g_q + (bh * T_ + tqb) * 8);
        float4 b0 = pb[0], b1 = pb[1];
        qq[0]=pack2(b0.x,b0.x); qq[1]=pack2(b0.y,b0.y); qq[2]=pack2(b0.z,b0.z); qq[3]=pack2(b0.w,b0.w);
        qq[4]=pack2(b1.x,b1.x); qq[5]=pack2(b1.y,b1.y); qq[6]=pack2(b1.z,b1.z); qq[7]=pack2(b1.w,b1.w);
    }

    u64 oa[4] = {0,0,0,0}, ob[4] = {0,0,0,0};
    float la = 0.f, lb = 0.f;

    const float4* vb4 = (const float4*)(g_v + bh * T_ * 8);
    const int bar = 1 + half;

    for (int kt = half; kt <= jhi; kt += 2) {
        const int s0 = kt * 128;
        {   // stage K transposed+key-paired: 2 threads per key pair
            const int t2 = ht >> 6, sp = ht & 63;
            const float4* kg = (const float4*)(g_k + (bh * T_ + s0 + 2 * sp) * 8 + t2 * 4);
            float4 ka = kg[0];       // key 2sp, 4 dims
            float4 kb = kg[2];       // key 2sp+1
            u64* row = (u64*)&sKp[half][sp * 20 + t2 * 8];
            row[0] = pack2(ka.x, kb.x); row[1] = pack2(ka.y, kb.y);
            row[2] = pack2(ka.z, kb.z); row[3] = pack2(ka.w, kb.w);
            sV[half][ht]       = vb4[s0 * 2 + ht];
            sV[half][ht + 128] = vb4[s0 * 2 + ht + 128];
        }
        asm volatile("bar.sync %0, 128;" :: "r"(bar) : "memory");

        if (kt < j) {
            // both queries, full
            #pragma unroll 2
            for (int sp = 0; sp < 64; sp++) {
                const ulonglong2* kr = (const ulonglong2*)&sKp[half][sp * 20];
                ulonglong2 kA = kr[0], kB = kr[1], kC = kr[2], kD = kr[3];
                const ulonglong2* vr = (const ulonglong2*)&sV[half][4 * sp];
                ulonglong2 va0 = vr[0], va1 = vr[1], vb0 = vr[2], vb1 = vr[3];
                attn_pair(qa, kA, kB, kC, kD, va0, va1, vb0, vb1, oa, la, true, true);
                attn_pair(qq, kA, kB, kC, kD, va0, va1, vb0, vb1, ob, lb, true, true);
            }
        } else if (kt == j) {
            // qa diagonal, qb full
            for (int sp = 0; sp < 64; sp++) {
                const ulonglong2* kr = (const ulonglong2*)&sKp[half][sp * 20];
                ulonglong2 kA = kr[0], kB = kr[1], kC = kr[2], kD = kr[3];
                const ulonglong2* vr = (const ulonglong2*)&sV[half][4 * sp];
                ulonglong2 va0 = vr[0], va1 = vr[1], vb0 = vr[2], vb1 = vr[3];
                attn_pair(qa, kA, kB, kC, kD, va0, va1, vb0, vb1, oa, la,
                          2 * sp <= ht, 2 * sp + 1 <= ht);
                attn_pair(qq, kA, kB, kC, kD, va0, va1, vb0, vb1, ob, lb, true, true);
            }
        } else if (kt < jhi) {
            // qb only, full
            #pragma unroll 2
            for (int sp = 0; sp < 64; sp++) {
                const ulonglong2* kr = (const ulonglong2*)&sKp[half][sp * 20];
                ulonglong2 kA = kr[0], kB = kr[1], kC = kr[2], kD = kr[3];
                const ulonglong2* vr = (const ulonglong2*)&sV[half][4 * sp];
                ulonglong2 va0 = vr[0], va1 = vr[1], vb0 = vr[2], vb1 = vr[3];
                attn_pair(qq, kA, kB, kC, kD, va0, va1, vb0, vb1, ob, lb, true, true);
            }
        } else {
            // qb diagonal
            for (int sp = 0; sp < 64; sp++) {
                const ulonglong2* kr = (const ulonglong2*)&sKp[half][sp * 20];
                ulonglong2 kA = kr[0], kB = kr[1], kC = kr[2], kD = kr[3];
                const ulonglong2* vr = (const ulonglong2*)&sV[half][4 * sp];
                ulonglong2 va0 = vr[0], va1 = vr[1], vb0 = vr[2], vb1 = vr[3];
                attn_pair(qq, kA, kB, kC, kD, va0, va1, vb0, vb1, ob, lb,
                          2 * sp <= ht, 2 * sp + 1 <= ht);
            }
        }
        asm volatile("bar.sync %0, 128;" :: "r"(bar) : "memory");
    }

    if (half == 1) {
        float* pb = &sPart[ht * 20];
        #pragma unroll
        for (int i = 0; i < 4; i++) {
            float2 u = unpack2(oa[i]); pb[2*i] = u.x; pb[2*i+1] = u.y;
            float2 w = unpack2(ob[i]); pb[8+2*i] = w.x; pb[8+2*i+1] = w.y;
        }
        pb[16] = la; pb[17] = lb;
    }
    __syncthreads();
    if (half == 0) {
        const float* pb = &sPart[ht * 20];
        float oav[8], obv[8];
        #pragma unroll
        for (int i = 0; i < 4; i++) {
            float2 u = unpack2(oa[i]); oav[2*i] = u.x + pb[2*i]; oav[2*i+1] = u.y + pb[2*i+1];
            float2 w = unpack2(ob[i]); obv[2*i] = w.x + pb[8+2*i]; obv[2*i+1] = w.y + pb[8+2*i+1];
        }
        const float ra = __fdividef(1.f, la + pb[16]);
        const float rb = __fdividef(1.f, lb + pb[17]);
        const int b = bh >> 2, h = bh & 3;
        float4* opa = (float4*)(g_o + (b * T_ + tqa) * 32 + h * 8);
        opa[0] = make_float4(oav[0]*ra, oav[1]*ra, oav[2]*ra, oav[3]*ra);
        opa[1] = make_float4(oav[4]*ra, oav[5]*ra, oav[6]*ra, oav[7]*ra);
        float4* opb = (float4*)(g_o + (b * T_ + tqb) * 32 + h * 8);
        opb[0] = make_float4(obv[0]*rb, obv[1]*rb, obv[2]*rb, obv[3]*rb);
        opb[1] = make_float4(obv[4]*rb, obv[5]*rb, obv[6]*rb, obv[7]*rb);
    }
}

// ---------------------------------------------------------------------------
// Kernel 3: proj + residual + LN2 + FFN + residual. 64 tokens, 256 threads.
// ---------------------------------------------------------------------------
constexpr int SM3_FLOATS = 1024 + 4096 + 4096 + 128 + 128 + 64 * 33 + 64 * 129;
constexpr int SM3_BYTES  = SM3_FLOATS * 4;

__global__ __launch_bounds__(256) void k_post(
    float* __restrict__ out,
    const float* __restrict__ Wp, const float* __restrict__ bp,
    const float* __restrict__ W1, const float* __restrict__ b1v,
    const float* __restrict__ W2, const float* __restrict__ b2v,
    const float* __restrict__ g2, const float* __restrict__ bt2)
{
    extern __shared__ float sm[];
    float* sWp  = sm;                 // [kd][32]
    float* sW1  = sWp + 1024;         // [k][128]
    float* sW2  = sW1 + 4096;         // [k][32]
    float* sB   = sW2 + 4096;         // 0:bproj 32:b2 64:ln2_g 96:ln2_b
    float* sb1  = sB + 128;
    float* sX   = sb1 + 128;          // 64 x 33
    float* sHid = sX + 64 * 33;       // 64 x 129

    const int tid = threadIdx.x;
    const int t0  = blockIdx.x * 64;

    for (int i = tid; i < 1024; i += 256) sWp[i] = Wp[i];
    for (int i = tid; i < 4096; i += 256) sW1[i] = W1[i];
    for (int i = tid; i < 4096; i += 256) sW2[i] = W2[i];
    if (tid < 32) { sB[tid] = bp[tid]; sB[32 + tid] = b2v[tid];
                    sB[64 + tid] = g2[tid]; sB[96 + tid] = bt2[tid]; }
    if (tid >= 128 && tid < 256) sb1[tid - 128] = b1v[tid - 128];

    for (int i = tid; i < 512; i += 256) {
        int row = i >> 3, c4 = i & 7;
        float4 v = ((const float4*)(g_o + (t0 + row) * 32))[c4];
        float* d = &sX[row * 33 + c4 * 4];
        d[0] = v.x; d[1] = v.y; d[2] = v.z; d[3] = v.w;
    }
    __syncthreads();

    // ---- stage A: x1 = h + o@Wproj + bproj ; h2 = LN2(x1) ----
    const int tr = tid >> 2, q4 = tid & 3;   // token, col-quarter (8 cols)
    const int gt = t0 + tr;
    u64 accp[4] = {0,0,0,0};

    #pragma unroll 4
    for (int kd = 0; kd < 32; kd++) {
        float a = sX[tr * 33 + kd];
        u64 ap = pack2(a, a);
        const ulonglong2* wr = (const ulonglong2*)&sWp[kd * 32 + q4 * 8];
        ulonglong2 w0 = wr[0], w1 = wr[1];
        accp[0] = ffma2(ap, w0.x, accp[0]); accp[1] = ffma2(ap, w0.y, accp[1]);
        accp[2] = ffma2(ap, w1.x, accp[2]); accp[3] = ffma2(ap, w1.y, accp[3]);
    }
    float xv[8];
    {
        const float4* hp = (const float4*)(g_h + gt * 32 + q4 * 8);
        float4 h0 = hp[0], h1 = hp[1];
        float hh[8] = {h0.x, h0.y, h0.z, h0.w, h1.x, h1.y, h1.z, h1.w};
        #pragma unroll
        for (int i = 0; i < 4; i++) {
            float2 u = unpack2(accp[i]);
            xv[2*i]   = hh[2*i]   + u.x + sB[q4 * 8 + 2*i];
            xv[2*i+1] = hh[2*i+1] + u.y + sB[q4 * 8 + 2*i + 1];
        }
    }
    float s = 0.f, ss = 0.f;
    #pragma unroll
    for (int i = 0; i < 8; i++) { s += xv[i]; ss += xv[i] * xv[i]; }
    s  += __shfl_xor_sync(0xffffffffu, s, 1);
    ss += __shfl_xor_sync(0xffffffffu, ss, 1);
    s  += __shfl_xor_sync(0xffffffffu, s, 2);
    ss += __shfl_xor_sync(0xffffffffu, ss, 2);
    const float mu = s * 0.03125f;
    const float rs = rsqrtf(ss * 0.03125f - mu * mu + 1e-5f);
    float h2r[8];
    #pragma unroll
    for (int i = 0; i < 8; i++)
        h2r[i] = (xv[i] - mu) * rs * sB[64 + q4 * 8 + i] + sB[96 + q4 * 8 + i];

    __syncthreads();
    #pragma unroll
    for (int i = 0; i < 8; i++) sX[tr * 33 + q4 * 8 + i] = h2r[i];
    __syncthreads();

    // ---- stage B: hid = relu(h2 @ W1 + b1) ----
    const int ttb = tid >> 4;   // 0..15 -> 4 tokens each
    const int oo  = tid & 15;   // 8 outs each
    u64 accB[4][4];
    #pragma unroll
    for (int j = 0; j < 4; j++)
        #pragma unroll
        for (int i = 0; i < 4; i++) accB[j][i] = 0;

    #pragma unroll 4
    for (int k = 0; k < 32; k++) {
        u64 ap[4];
        #pragma unroll
        for (int j = 0; j < 4; j++) {
            float a = sX[(ttb * 4 + j) * 33 + k];
            ap[j] = pack2(a, a);
        }
        const ulonglong2* wr = (const ulonglong2*)&sW1[k * 128 + oo * 8];
        ulonglong2 ww0 = wr[0], ww1 = wr[1];
        u64 wv[4] = {ww0.x, ww0.y, ww1.x, ww1.y};
        #pragma unroll
        for (int j = 0; j < 4; j++)
            #pragma unroll
            for (int i = 0; i < 4; i++)
                accB[j][i] = ffma2(ap[j], wv[i], accB[j][i]);
    }
    #pragma unroll
    for (int j = 0; j < 4; j++)
        #pragma unroll
        for (int i = 0; i < 4; i++) {
            float2 u = unpack2(accB[j][i]);
            float* d = &sHid[(ttb * 4 + j) * 129 + oo * 8 + 2 * i];
            d[0] = fmaxf(u.x + sb1[oo * 8 + 2 * i], 0.f);
            d[1] = fmaxf(u.y + sb1[oo * 8 + 2 * i + 1], 0.f);
        }
    __syncthreads();

    // ---- stage C: out = h2 + hid @ W2 + b2 ----
    u64 accC[4] = {0,0,0,0};
    #pragma unroll 4
    for (int k = 0; k < 128; k++) {
        float a = sHid[tr * 129 + k];
        u64 ap = pack2(a, a);
        const ulonglong2* wr = (const ulonglong2*)&sW2[k * 32 + q4 * 8];
        ulonglong2 w0 = wr[0], w1 = wr[1];
        accC[0] = ffma2(ap, w0.x, accC[0]); accC[1] = ffma2(ap, w0.y, accC[1]);
        accC[2] = ffma2(ap, w1.x, accC[2]); accC[3] = ffma2(ap, w1.y, accC[3]);
    }
    float cc[8];
    #pragma unroll
    for (int i = 0; i < 4; i++) {
        float2 u = unpack2(accC[i]);
        cc[2*i] = u.x; cc[2*i+1] = u.y;
    }
    float4* op = (float4*)(out + gt * 32 + q4 * 8);
    const float* b2p = &sB[32 + q4 * 8];
    op[0] = make_float4(h2r[0] + cc[0] + b2p[0], h2r[1] + cc[1] + b2p[1],
                        h2r[2] + cc[2] + b2p[2], h2r[3] + cc[3] + b2p[3]);
    op[1] = make_float4(h2r[4] + cc[4] + b2p[4], h2r[5] + cc[5] + b2p[5],
                        h2r[6] + cc[6] + b2p[6], h2r[7] + cc[7] + b2p[7]);
}

// ---------------------------------------------------------------------------
extern "C" void kernel_launch(void* const* d_in, const int* in_sizes, int n_in,
                              void* d_out, int out_size)
{
    const float* x   = (const float*)d_in[0];
    const float* Wq  = (const float*)d_in[1];
    const float* Wk  = (const float*)d_in[2];
    const float* Wv  = (const float*)d_in[3];
    const float* Wp  = (const float*)d_in[4];
    const float* bp  = (const float*)d_in[5];
    const float* g1  = (const float*)d_in[6];
    const float* b1  = (const float*)d_in[7];
    const float* W1  = (const float*)d_in[8];
    const float* b1f = (const float*)d_in[9];
    const float* W2  = (const float*)d_in[10];
    const float* b2f = (const float*)d_in[11];
    const float* g2  = (const float*)d_in[12];
    const float* bt2 = (const float*)d_in[13];
    float* out = (float*)d_out;

    cudaFuncSetAttribute((const void*)k_post,
                         cudaFuncAttributeMaxDynamicSharedMemorySize, SM3_BYTES);

    k_ln_qkv<<<BT_ / 32, 128>>>(x, Wq, Wk, Wv, g1, b1);

    dim3 ga(B_ * 4, 8);
    k_attn<<<ga, 256>>>();

    k_post<<<BT_ / 64, 256, SM3_BYTES>>>(out, Wp, bp, W1, b1f, W2, b2f, g2, bt2);
}